// round 9
// baseline (speedup 1.0000x reference)
#include <cuda_runtime.h>
#include <cuda_fp16.h>
#include <cstdint>
#include <cstddef>

// ============================================================================
// B=16, W_DIM=512, C=1024, H=W=64  -> GEMM: M=65536, N=1024, K=1024 (fp16 in)
// compute_103 PTX target: no tcgen05 -> mma.sync HMMA + cp.async + ldmatrix.
// R9: fp16-accumulate MMA (rt=8, 2x rate) + per-iter promotion to f32 masters.
// ============================================================================

__device__ float4  g_params[16 * 1024];                  // fx*2pi, fy*2pi, ph*2pi, amp
__device__ __half  g_feat[(size_t)65536 * 1024];         // fp16 features, K-major
__device__ __half  g_wt[(size_t)1024 * 1024];            // fp16 weight/32, K-major

__device__ __forceinline__ uint32_t smem_u32(const void* p) {
    uint32_t a;
    asm("{ .reg .u64 t; cvta.to.shared.u64 t, %1; cvt.u32.u64 %0, t; }" : "=r"(a) : "l"(p));
    return a;
}
__device__ __forceinline__ void cp_async16(uint32_t dst, const void* src) {
    asm volatile("cp.async.cg.shared.global [%0], [%1], 16;\n" :: "r"(dst), "l"(src));
}
__device__ __forceinline__ void cp_commit() { asm volatile("cp.async.commit_group;\n" ::: "memory"); }
template <int N> __device__ __forceinline__ void cp_wait() {
    asm volatile("cp.async.wait_group %0;\n" :: "n"(N) : "memory");
}
__device__ __forceinline__ void ldsm_x4(uint32_t& r0, uint32_t& r1, uint32_t& r2, uint32_t& r3,
                                        uint32_t addr) {
    asm volatile("ldmatrix.sync.aligned.m8n8.x4.shared.b16 {%0,%1,%2,%3}, [%4];"
                 : "=r"(r0), "=r"(r1), "=r"(r2), "=r"(r3) : "r"(addr));
}

// ============================================================================
// Kernel 1: per-batch affine + per-channel params  (grid 16, 128 thr)
// ============================================================================
__global__ void k_setup(const float* __restrict__ w, const float* __restrict__ freqs,
                        const float* __restrict__ phases, const float* __restrict__ affine_w,
                        const float* __restrict__ affine_b) {
    __shared__ float t_sm[4];
    __shared__ float cs[4];
    int b = blockIdx.x;
    int tid = threadIdx.x, wid = tid >> 5, lane = tid & 31;

    float sum = 0.f;
    const float* wr = w + b * 512;
    const float* ar = affine_w + wid * 512;
    for (int j = lane; j < 512; j += 32) sum += wr[j] * ar[j];
    for (int o = 16; o; o >>= 1) sum += __shfl_xor_sync(0xffffffffu, sum, o);
    if (lane == 0) t_sm[wid] = sum * (1.0f / 22.627416997969522f) + affine_b[wid];
    __syncthreads();
    if (tid == 0) {
        float t0 = t_sm[0], t1 = t_sm[1], t2 = t_sm[2], t3 = t_sm[3];
        float inv = rsqrtf(t0 * t0 + t1 * t1);
        float c = t0 * inv, s = t1 * inv, tx = t2 * inv, ty = t3 * inv;
        cs[0] = c; cs[1] = s;
        cs[2] = -(c * tx - s * ty);   // trans_x
        cs[3] = -(s * tx + c * ty);   // trans_y
    }
    __syncthreads();
    float c = cs[0], s = cs[1], trx = cs[2], tryy = cs[3];
    const float TWO_PI = 6.283185307179586f;
    for (int ch = tid; ch < 1024; ch += 128) {
        float fx = freqs[ch * 2], fy = freqs[ch * 2 + 1];
        float ph = phases[ch] + fx * trx + fy * tryy;      // original freqs here
        float fbx = fx * c + fy * s;                        // f @ R
        float fby = -fx * s + fy * c;
        float r = sqrtf(fbx * fbx + fby * fby);
        float amp = 1.0f - (r - 2.0f) * (1.0f / 30.0f);
        amp = fminf(fmaxf(amp, 0.0f), 1.0f);
        g_params[b * 1024 + ch] = make_float4(fbx * TWO_PI, fby * TWO_PI, ph * TWO_PI, amp);
    }
}

// ============================================================================
// Kernel 2: weight -> fp16 * (1/sqrt(1024))
// ============================================================================
__global__ __launch_bounds__(256) void k_wt(const float* __restrict__ wt) {
    size_t i = (size_t)blockIdx.x * 256 + threadIdx.x;
    g_wt[i] = __float2half(wt[i] * 0.03125f);
}

// ============================================================================
// Kernel 3: fp16 feature map.  block = (b,h): m = b*4096 + h*64 + w
// ============================================================================
__global__ __launch_bounds__(256) void k_feat() {
    __shared__ float sfx[1024], sbase[1024], samp[1024];
    int bx = blockIdx.x;
    int b = bx >> 6, h = bx & 63;
    int tid = threadIdx.x;
    float v = (h + 0.5f) * (1.0f / 64.0f) - 0.5f;
    for (int ch = tid; ch < 1024; ch += 256) {
        float4 p = g_params[b * 1024 + ch];
        sfx[ch] = p.x;
        sbase[ch] = p.y * v + p.z;
        samp[ch] = p.w;
    }
    __syncthreads();
    int c0 = tid * 4;
    float fx0 = sfx[c0], fx1 = sfx[c0 + 1], fx2 = sfx[c0 + 2], fx3 = sfx[c0 + 3];
    float b0 = sbase[c0], b1 = sbase[c0 + 1], b2 = sbase[c0 + 2], b3 = sbase[c0 + 3];
    float a0 = samp[c0], a1 = samp[c0 + 1], a2 = samp[c0 + 2], a3 = samp[c0 + 3];
    __half* outp = g_feat + (size_t)bx * 64 * 1024 + c0;
#pragma unroll 4
    for (int wq = 0; wq < 64; wq++) {
        float u = (wq + 0.5f) * (1.0f / 64.0f) - 0.5f;
        float s0 = __sinf(fmaf(fx0, u, b0)) * a0;
        float s1 = __sinf(fmaf(fx1, u, b1)) * a1;
        float s2 = __sinf(fmaf(fx2, u, b2)) * a2;
        float s3 = __sinf(fmaf(fx3, u, b3)) * a3;
        union { __half2 h2[2]; uint2 u2; } cv;
        cv.h2[0] = __floats2half2_rn(s0, s1);
        cv.h2[1] = __floats2half2_rn(s2, s3);
        *reinterpret_cast<uint2*>(outp + (size_t)wq * 1024) = cv.u2;
    }
}

// ============================================================================
// Kernel 4: fp16 mma.sync GEMM.  C[m,n] = sum_k A[m,k]*B[n,k]
//   BM=128, BN=256, BK=64. 3-stage cp.async. 8 warps (2 M x 4 N), warp 64x64.
//   fp16 accumulate within one BK=64 slice, promote to f32 each iteration.
//   Rows padded to 72 halves (144B stride == 4 banks mod 32 -> LDSM conflict-free).
// ============================================================================
#define BM 128
#define BN 256
#define AROW 72
#define ROWB (AROW * 2)                       // 144 bytes per smem row
#define A_TILE_H (BM * AROW)                  // 9216 halves
#define B_TILE_H (BN * AROW)                  // 18432 halves
#define STAGE_H (A_TILE_H + B_TILE_H)         // 27648 halves (55296 B)
#define NST 3
#define GEMM_SMEM (NST * STAGE_H * 2)         // 165888 bytes

__device__ __forceinline__ void load_stage(uint32_t st, const __half* Ag,
                                           const __half* Bg, int tid) {
#pragma unroll
    for (int t = 0; t < 4; t++) {             // A: 128 rows x 8 chunks = 1024
        int cid = tid + t * 256;
        int row = cid >> 3, j = cid & 7;
        cp_async16(st + row * ROWB + j * 16, Ag + (size_t)row * 1024 + j * 8);
    }
    uint32_t stB = st + A_TILE_H * 2;
#pragma unroll
    for (int t = 0; t < 8; t++) {             // B: 256 rows x 8 chunks = 2048
        int cid = tid + t * 256;
        int row = cid >> 3, j = cid & 7;
        cp_async16(stB + row * ROWB + j * 16, Bg + (size_t)row * 1024 + j * 8);
    }
}

__global__ __launch_bounds__(256, 1) void k_gemm(float* __restrict__ out) {
    extern __shared__ __half smem_h[];
    uint32_t sb = smem_u32(smem_h);
    int tid = threadIdx.x, wid = tid >> 5, lane = tid & 31;
    int warp_m = wid >> 2;        // 0..1  (64 rows each)
    int warp_n = wid & 3;         // 0..3  (64 cols each)
    int g = lane >> 2;            // groupID 0..7
    int kq = lane & 3;            // thread-in-group

    int n0 = blockIdx.x * BN;
    int m0 = blockIdx.y * BM;

    const __half* Abase = g_feat + (size_t)m0 * 1024;
    const __half* Bbase = g_wt + (size_t)n0 * 1024;

    const uint32_t a_lane_off = (uint32_t)(warp_m * 64 + (lane & 15)) * ROWB + (lane >> 4) * 16;
    const uint32_t b_lane_off = (uint32_t)(warp_n * 64 + (lane & 15)) * ROWB + (lane >> 4) * 16;

    float acc[4][8][4];           // f32 masters
#pragma unroll
    for (int mt = 0; mt < 4; mt++)
#pragma unroll
        for (int nt = 0; nt < 8; nt++)
#pragma unroll
            for (int r = 0; r < 4; r++) acc[mt][nt][r] = 0.f;

    uint32_t cacc[4][8][2];       // fp16 chunk accumulators (2 b32 = 4 halves)
    uint32_t afr[4][4], bfr[4][4];

    // prologue: stages 0,1
    load_stage(sb, Abase, Bbase, tid);
    cp_commit();
    load_stage(sb + STAGE_H * 2, Abase + 64, Bbase + 64, tid);
    cp_commit();

    for (int i = 0; i < 16; i++) {
        if (i < 15) cp_wait<1>(); else cp_wait<0>();
        __syncthreads();
        if (i + 2 < 16) {
            load_stage(sb + ((i + 2) % NST) * (STAGE_H * 2),
                       Abase + (size_t)(i + 2) * 64, Bbase + (size_t)(i + 2) * 64, tid);
            cp_commit();
        }
        uint32_t As = sb + (i % NST) * (STAGE_H * 2);
        uint32_t a_base = As + a_lane_off;
        uint32_t b_base = As + A_TILE_H * 2 + b_lane_off;

#pragma unroll
        for (int ks = 0; ks < 4; ks++) {
#pragma unroll
            for (int mt = 0; mt < 4; mt++)
                ldsm_x4(afr[mt][0], afr[mt][1], afr[mt][2], afr[mt][3],
                        a_base + mt * (16 * ROWB) + ks * 32);
#pragma unroll
            for (int nb = 0; nb < 4; nb++)
                ldsm_x4(bfr[nb][0], bfr[nb][1], bfr[nb][2], bfr[nb][3],
                        b_base + nb * (16 * ROWB) + ks * 32);

            if (ks == 0) {
#pragma unroll
                for (int mt = 0; mt < 4; mt++)
#pragma unroll
                    for (int nt = 0; nt < 8; nt++)
                        asm volatile(
                            "mma.sync.aligned.m16n8k16.row.col.f16.f16.f16.f16 "
                            "{%0,%1}, {%2,%3,%4,%5}, {%6,%7}, {%8,%8};"
                            : "=r"(cacc[mt][nt][0]), "=r"(cacc[mt][nt][1])
                            : "r"(afr[mt][0]), "r"(afr[mt][1]),
                              "r"(afr[mt][2]), "r"(afr[mt][3]),
                              "r"(bfr[nt >> 1][nt & 1]), "r"(bfr[nt >> 1][(nt & 1) + 2]),
                              "r"(0u));
            } else {
#pragma unroll
                for (int mt = 0; mt < 4; mt++)
#pragma unroll
                    for (int nt = 0; nt < 8; nt++)
                        asm volatile(
                            "mma.sync.aligned.m16n8k16.row.col.f16.f16.f16.f16 "
                            "{%0,%1}, {%2,%3,%4,%5}, {%6,%7}, {%0,%1};"
                            : "+r"(cacc[mt][nt][0]), "+r"(cacc[mt][nt][1])
                            : "r"(afr[mt][0]), "r"(afr[mt][1]),
                              "r"(afr[mt][2]), "r"(afr[mt][3]),
                              "r"(bfr[nt >> 1][nt & 1]), "r"(bfr[nt >> 1][(nt & 1) + 2]));
            }
        }

        // promote fp16 chunk sums into f32 masters
#pragma unroll
        for (int mt = 0; mt < 4; mt++)
#pragma unroll
            for (int nt = 0; nt < 8; nt++) {
                float2 lo = __half22float2(*reinterpret_cast<__half2*>(&cacc[mt][nt][0]));
                float2 hi = __half22float2(*reinterpret_cast<__half2*>(&cacc[mt][nt][1]));
                acc[mt][nt][0] += lo.x;
                acc[mt][nt][1] += lo.y;
                acc[mt][nt][2] += hi.x;
                acc[mt][nt][3] += hi.y;
            }
    }

    // Epilogue. c0:(row g, col 2kq) c1:(g, 2kq+1) c2:(g+8, 2kq) c3:(g+8, 2kq+1)
    // out[b][n][hw]: b = m0>>12 (const per CTA), hw = m & 4095.
    int b = m0 >> 12;
#pragma unroll
    for (int mt = 0; mt < 4; mt++) {
        int m_lo = m0 + warp_m * 64 + mt * 16 + g;
        int hw0 = m_lo & 4095;
        int hw1 = hw0 + 8;
#pragma unroll
        for (int nt = 0; nt < 8; nt++) {
            int n = n0 + warp_n * 64 + nt * 8 + kq * 2;
            float* o0 = out + ((size_t)(b * 1024 + n)) * 4096;
            float* o1 = o0 + 4096;
            o0[hw0] = acc[mt][nt][0];
            o1[hw0] = acc[mt][nt][1];
            o0[hw1] = acc[mt][nt][2];
            o1[hw1] = acc[mt][nt][3];
        }
    }
}

// ============================================================================
// launch
// ============================================================================
extern "C" void kernel_launch(void* const* d_in, const int* in_sizes, int n_in,
                              void* d_out, int out_size) {
    const float* w        = (const float*)d_in[0];
    const float* freqs    = (const float*)d_in[1];
    const float* phases   = (const float*)d_in[2];
    const float* weight   = (const float*)d_in[3];
    const float* affine_w = (const float*)d_in[4];
    const float* affine_b = (const float*)d_in[5];
    float* out = (float*)d_out;

    cudaFuncSetAttribute(k_gemm, cudaFuncAttributeMaxDynamicSharedMemorySize, GEMM_SMEM);

    k_setup<<<16, 128>>>(w, freqs, phases, affine_w, affine_b);
    k_wt<<<4096, 256>>>(weight);
    k_feat<<<1024, 256>>>();
    k_gemm<<<dim3(4, 512), 256, GEMM_SMEM>>>(out);
}

// round 11
// speedup vs baseline: 1.6387x; 1.6387x over previous
#include <cuda_runtime.h>
#include <cuda_fp16.h>
#include <cstdint>
#include <cstddef>
#include <math.h>

// ============================================================================
// B=16, C=1024, H=W=64.  |freqs| <= 2 cycles/unit, u,v in (-0.5,0.5)
//  -> each spatial phasor e^{i2pi f u} lies in a 16-dim Chebyshev subspace
//     (error ~ (2pi)^16/(2^15 16!) ~ 8.6e-6).
// out[b,n,h,w] = sum_{p,q} U[h,p] U[w,q] S[b,p,q,n]
//   S[b,p,q,n] = sum_c W'[n,c] amp_c sin(2pi(fx t_q + fy t_p + ph))
// S via fp16 mma GEMM: M = 16*256 = 4096 (16x fewer MACs than dense),
// then a separable fp32 interpolation writes the 256MB output.
// ============================================================================
#define R 16

__device__ float4  g_params[16 * 1024];               // fx*2pi, fy*2pi, ph*2pi, amp
__device__ __half  g_vfeat[(size_t)4096 * 1024];      // virtual features (Cheb nodes)
__device__ __half  g_wt[(size_t)1024 * 1024];         // fp16 weight/32, K-major
__device__ float   g_S[(size_t)4096 * 1024];          // S[b][p][q][n]
__device__ float   g_U[64 * R];                       // Lagrange basis at pixels

__device__ __forceinline__ uint32_t smem_u32(const void* p) {
    uint32_t a;
    asm("{ .reg .u64 t; cvta.to.shared.u64 t, %1; cvt.u32.u64 %0, t; }" : "=r"(a) : "l"(p));
    return a;
}
__device__ __forceinline__ void cp_async16(uint32_t dst, const void* src) {
    asm volatile("cp.async.cg.shared.global [%0], [%1], 16;\n" :: "r"(dst), "l"(src));
}
__device__ __forceinline__ void cp_commit() { asm volatile("cp.async.commit_group;\n" ::: "memory"); }
template <int N> __device__ __forceinline__ void cp_wait() {
    asm volatile("cp.async.wait_group %0;\n" :: "n"(N) : "memory");
}
__device__ __forceinline__ void ldsm_x4(uint32_t& r0, uint32_t& r1, uint32_t& r2, uint32_t& r3,
                                        uint32_t addr) {
    asm volatile("ldmatrix.sync.aligned.m8n8.x4.shared.b16 {%0,%1,%2,%3}, [%4];"
                 : "=r"(r0), "=r"(r1), "=r"(r2), "=r"(r3) : "r"(addr));
}

// ============================================================================
// Kernel 1: per-batch affine + per-channel params  (grid 16, 128 thr)
// ============================================================================
__global__ void k_setup(const float* __restrict__ w, const float* __restrict__ freqs,
                        const float* __restrict__ phases, const float* __restrict__ affine_w,
                        const float* __restrict__ affine_b) {
    __shared__ float t_sm[4];
    __shared__ float cs[4];
    int b = blockIdx.x;
    int tid = threadIdx.x, wid = tid >> 5, lane = tid & 31;

    float sum = 0.f;
    const float* wr = w + b * 512;
    const float* ar = affine_w + wid * 512;
    for (int j = lane; j < 512; j += 32) sum += wr[j] * ar[j];
    for (int o = 16; o; o >>= 1) sum += __shfl_xor_sync(0xffffffffu, sum, o);
    if (lane == 0) t_sm[wid] = sum * (1.0f / 22.627416997969522f) + affine_b[wid];
    __syncthreads();
    if (tid == 0) {
        float t0 = t_sm[0], t1 = t_sm[1], t2 = t_sm[2], t3 = t_sm[3];
        float inv = rsqrtf(t0 * t0 + t1 * t1);
        float c = t0 * inv, s = t1 * inv, tx = t2 * inv, ty = t3 * inv;
        cs[0] = c; cs[1] = s;
        cs[2] = -(c * tx - s * ty);   // trans_x
        cs[3] = -(s * tx + c * ty);   // trans_y
    }
    __syncthreads();
    float c = cs[0], s = cs[1], trx = cs[2], tryy = cs[3];
    const float TWO_PI = 6.283185307179586f;
    for (int ch = tid; ch < 1024; ch += 128) {
        float fx = freqs[ch * 2], fy = freqs[ch * 2 + 1];
        float ph = phases[ch] + fx * trx + fy * tryy;      // original freqs here
        float fbx = fx * c + fy * s;                        // f @ R
        float fby = -fx * s + fy * c;
        float r = sqrtf(fbx * fbx + fby * fby);
        float amp = 1.0f - (r - 2.0f) * (1.0f / 30.0f);
        amp = fminf(fmaxf(amp, 0.0f), 1.0f);
        g_params[b * 1024 + ch] = make_float4(fbx * TWO_PI, fby * TWO_PI, ph * TWO_PI, amp);
    }
}

// ============================================================================
// Kernel 2: weight -> fp16 * (1/sqrt(1024))
// ============================================================================
__global__ __launch_bounds__(256) void k_wt(const float* __restrict__ wt) {
    size_t i = (size_t)blockIdx.x * 256 + threadIdx.x;
    g_wt[i] = __float2half(wt[i] * 0.03125f);
}

// ============================================================================
// Kernel 3: Lagrange basis U[w][q] at Chebyshev nodes (barycentric, fp64)
// ============================================================================
__global__ void k_U() {
    int w = threadIdx.x;                       // 64 threads
    double x = (w + 0.5) / 64.0 - 0.5;
    double t[R], lam[R];
#pragma unroll
    for (int q = 0; q < R; q++) {
        double a = M_PI * (2 * q + 1) / (2.0 * R);
        t[q] = 0.5 * cos(a);
        lam[q] = ((q & 1) ? -1.0 : 1.0) * sin(a);
    }
    double D = 0.0;
#pragma unroll
    for (int q = 0; q < R; q++) D += lam[q] / (x - t[q]);
#pragma unroll
    for (int q = 0; q < R; q++)
        g_U[w * R + q] = (float)((lam[q] / (x - t[q])) / D);
}

// ============================================================================
// Kernel 4: virtual features at node pairs.  row m = b*256 + p*16 + q
//   vfeat[m][c] = amp * sin(fx2pi*t_q + fy2pi*t_p + ph2pi)
// ============================================================================
__global__ __launch_bounds__(256) void k_vf() {
    __shared__ float ts[R];
    int b = blockIdx.x, tid = threadIdx.x;
    if (tid < R) ts[tid] = 0.5f * cospif((2 * tid + 1) / (2.0f * R));
    __syncthreads();
    int c0 = tid * 4;
    float4 P[4];
#pragma unroll
    for (int j = 0; j < 4; j++) P[j] = g_params[b * 1024 + c0 + j];
    __half* outp = g_vfeat + (size_t)b * 256 * 1024 + c0;
    for (int r = 0; r < 256; r++) {
        float tq = ts[r & 15], tp = ts[r >> 4];
        float s0 = P[0].w * __sinf(P[0].x * tq + P[0].y * tp + P[0].z);
        float s1 = P[1].w * __sinf(P[1].x * tq + P[1].y * tp + P[1].z);
        float s2 = P[2].w * __sinf(P[2].x * tq + P[2].y * tp + P[2].z);
        float s3 = P[3].w * __sinf(P[3].x * tq + P[3].y * tp + P[3].z);
        union { __half2 h2[2]; uint2 u2; } cv;
        cv.h2[0] = __floats2half2_rn(s0, s1);
        cv.h2[1] = __floats2half2_rn(s2, s3);
        *reinterpret_cast<uint2*>(outp + (size_t)r * 1024) = cv.u2;
    }
}

// ============================================================================
// Kernel 5: S-GEMM (R8 pipeline).  S[m,n] = sum_k vfeat[m,k]*wt[n,k]
//   M=4096, N=1024, K=1024.  BM=128, BN=256, 8 warps 64x64, fp32 acc.
// ============================================================================
#define BM 128
#define BN 256
#define AROW 72
#define ROWB (AROW * 2)
#define A_TILE_H (BM * AROW)
#define B_TILE_H (BN * AROW)
#define STAGE_H (A_TILE_H + B_TILE_H)
#define NST 3
#define GEMM_SMEM (NST * STAGE_H * 2)

__device__ __forceinline__ void load_stage(uint32_t st, const __half* Ag,
                                           const __half* Bg, int tid) {
#pragma unroll
    for (int t = 0; t < 4; t++) {
        int cid = tid + t * 256;
        int row = cid >> 3, j = cid & 7;
        cp_async16(st + row * ROWB + j * 16, Ag + (size_t)row * 1024 + j * 8);
    }
    uint32_t stB = st + A_TILE_H * 2;
#pragma unroll
    for (int t = 0; t < 8; t++) {
        int cid = tid + t * 256;
        int row = cid >> 3, j = cid & 7;
        cp_async16(stB + row * ROWB + j * 16, Bg + (size_t)row * 1024 + j * 8);
    }
}

__global__ __launch_bounds__(256, 1) void k_gemm() {
    extern __shared__ __half smem_h[];
    uint32_t sb = smem_u32(smem_h);
    int tid = threadIdx.x, wid = tid >> 5, lane = tid & 31;
    int warp_m = wid >> 2, warp_n = wid & 3;
    int g = lane >> 2, kq = lane & 3;

    int n0 = blockIdx.x * BN;
    int m0 = blockIdx.y * BM;

    const __half* Abase = g_vfeat + (size_t)m0 * 1024;
    const __half* Bbase = g_wt + (size_t)n0 * 1024;

    const uint32_t a_lane_off = (uint32_t)(warp_m * 64 + (lane & 15)) * ROWB + (lane >> 4) * 16;
    const uint32_t b_lane_off = (uint32_t)(warp_n * 64 + (lane & 15)) * ROWB + (lane >> 4) * 16;

    float acc[4][8][4];
#pragma unroll
    for (int mt = 0; mt < 4; mt++)
#pragma unroll
        for (int nt = 0; nt < 8; nt++)
#pragma unroll
            for (int r = 0; r < 4; r++) acc[mt][nt][r] = 0.f;

    uint32_t afr[2][4][4], bfr[2][4][4];

    load_stage(sb, Abase, Bbase, tid);
    cp_commit();
    load_stage(sb + STAGE_H * 2, Abase + 64, Bbase + 64, tid);
    cp_commit();

#define LOAD_FRAGS(buf, abase_, bbase_, ksv)                                       \
    {                                                                              \
        _Pragma("unroll")                                                          \
        for (int mt = 0; mt < 4; mt++)                                             \
            ldsm_x4(afr[buf][mt][0], afr[buf][mt][1], afr[buf][mt][2],             \
                    afr[buf][mt][3], (abase_) + mt * (16 * ROWB) + (ksv) * 32);    \
        _Pragma("unroll")                                                          \
        for (int nb = 0; nb < 4; nb++)                                             \
            ldsm_x4(bfr[buf][nb][0], bfr[buf][nb][1], bfr[buf][nb][2],             \
                    bfr[buf][nb][3], (bbase_) + nb * (16 * ROWB) + (ksv) * 32);    \
    }

    for (int i = 0; i < 16; i++) {
        if (i < 15) cp_wait<1>(); else cp_wait<0>();
        __syncthreads();
        if (i + 2 < 16) {
            load_stage(sb + ((i + 2) % NST) * (STAGE_H * 2),
                       Abase + (size_t)(i + 2) * 64, Bbase + (size_t)(i + 2) * 64, tid);
            cp_commit();
        }
        uint32_t As = sb + (i % NST) * (STAGE_H * 2);
        uint32_t a_base = As + a_lane_off;
        uint32_t b_base = As + A_TILE_H * 2 + b_lane_off;

        LOAD_FRAGS(0, a_base, b_base, 0)
#pragma unroll
        for (int ks = 0; ks < 4; ks++) {
            int cur = ks & 1;
            if (ks < 3) LOAD_FRAGS(cur ^ 1, a_base, b_base, ks + 1)
#pragma unroll
            for (int mt = 0; mt < 4; mt++)
#pragma unroll
                for (int nt = 0; nt < 8; nt++)
                    asm volatile(
                        "mma.sync.aligned.m16n8k16.row.col.f32.f16.f16.f32 "
                        "{%0,%1,%2,%3}, {%4,%5,%6,%7}, {%8,%9}, {%0,%1,%2,%3};"
                        : "+f"(acc[mt][nt][0]), "+f"(acc[mt][nt][1]),
                          "+f"(acc[mt][nt][2]), "+f"(acc[mt][nt][3])
                        : "r"(afr[cur][mt][0]), "r"(afr[cur][mt][1]),
                          "r"(afr[cur][mt][2]), "r"(afr[cur][mt][3]),
                          "r"(bfr[cur][nt >> 1][nt & 1]),
                          "r"(bfr[cur][nt >> 1][(nt & 1) + 2]));
        }
    }

    // Epilogue: plain row-major S[m][n]
#pragma unroll
    for (int mt = 0; mt < 4; mt++) {
        int m_lo = m0 + warp_m * 64 + mt * 16 + g;
        float* o0 = g_S + (size_t)m_lo * 1024;
        float* o1 = o0 + 8 * 1024;
#pragma unroll
        for (int nt = 0; nt < 8; nt++) {
            int n = n0 + warp_n * 64 + nt * 8 + kq * 2;
            o0[n] = acc[mt][nt][0];
            o0[n + 1] = acc[mt][nt][1];
            o1[n] = acc[mt][nt][2];
            o1[n + 1] = acc[mt][nt][3];
        }
    }
}

// ============================================================================
// Kernel 6: separable interpolation.  out[b,n,h,w] = U[h,:] S[b,:,:,n] U[w,:]^T
//   grid (32 nch, 16 b), 256 thr. thread = (n_local, h-group of 8).
// ============================================================================
__global__ __launch_bounds__(256) void k_interp(float* __restrict__ out) {
    __shared__ float Ss[R][R][32];          // [p][q][n_local]
    __shared__ float Us[64][R];
    int b = blockIdx.y, n0 = blockIdx.x * 32;
    int tid = threadIdx.x;
    for (int idx = tid; idx < R * R * 32; idx += 256) {
        int p = idx >> 9, q = (idx >> 5) & 15, nl = idx & 31;
        Ss[p][q][nl] = g_S[(size_t)((b * 16 + p) * 16 + q) * 1024 + n0 + nl];
    }
    for (int idx = tid; idx < 64 * R; idx += 256)
        Us[idx >> 4][idx & 15] = g_U[idx];
    __syncthreads();

    int nl = tid & 31, hg = tid >> 5;
    float* obase = out + ((size_t)(b * 1024 + n0 + nl)) * 4096;
#pragma unroll 1
    for (int hh = 0; hh < 8; hh++) {
        int h = hg * 8 + hh;
        float z[R];
#pragma unroll
        for (int q = 0; q < R; q++) {
            float s = 0.f;
#pragma unroll
            for (int p = 0; p < R; p++) s += Us[h][p] * Ss[p][q][nl];
            z[q] = s;
        }
        float* orow = obase + h * 64;
#pragma unroll 4
        for (int w = 0; w < 64; w += 4) {
            float4 o;
            float a0 = 0.f, a1 = 0.f, a2 = 0.f, a3 = 0.f;
#pragma unroll
            for (int q = 0; q < R; q++) {
                a0 += Us[w][q] * z[q];
                a1 += Us[w + 1][q] * z[q];
                a2 += Us[w + 2][q] * z[q];
                a3 += Us[w + 3][q] * z[q];
            }
            o.x = a0; o.y = a1; o.z = a2; o.w = a3;
            *reinterpret_cast<float4*>(orow + w) = o;
        }
    }
}

// ============================================================================
// launch
// ============================================================================
extern "C" void kernel_launch(void* const* d_in, const int* in_sizes, int n_in,
                              void* d_out, int out_size) {
    const float* w        = (const float*)d_in[0];
    const float* freqs    = (const float*)d_in[1];
    const float* phases   = (const float*)d_in[2];
    const float* weight   = (const float*)d_in[3];
    const float* affine_w = (const float*)d_in[4];
    const float* affine_b = (const float*)d_in[5];
    float* out = (float*)d_out;

    cudaFuncSetAttribute(k_gemm, cudaFuncAttributeMaxDynamicSharedMemorySize, GEMM_SMEM);

    k_setup<<<16, 128>>>(w, freqs, phases, affine_w, affine_b);
    k_wt<<<4096, 256>>>(weight);
    k_U<<<1, 64>>>();
    k_vf<<<16, 256>>>();
    k_gemm<<<dim3(4, 32), 256, GEMM_SMEM>>>();
    k_interp<<<dim3(32, 16), 256>>>(out);
}

// round 12
// speedup vs baseline: 1.7599x; 1.0739x over previous
#include <cuda_runtime.h>
#include <cuda_fp16.h>
#include <cstdint>
#include <cstddef>
#include <math.h>

// ============================================================================
// B=16, C=1024, H=W=64.  |freqs| <= 2  -> rank-16 Chebyshev separable form:
//   out[b,n,h,w] = sum_{p,q} U[h,p] U[w,q] S[b,p,q,n]
// S via fp16 HMMA GEMM at 16x16 Chebyshev node pairs (16x fewer MACs),
// then LDS-optimized separable fp32 interpolation writes the 256MB output.
// ============================================================================
#define R 16

__device__ float4  g_params[16 * 1024];               // fx*2pi, fy*2pi, ph*2pi, amp
__device__ __half  g_vfeat[(size_t)4096 * 1024];      // virtual features (Cheb nodes)
__device__ __half  g_wt[(size_t)1024 * 1024];         // fp16 weight/32, K-major
__device__ float   g_S[(size_t)4096 * 1024];          // S[b][p][q][n]
__device__ float   g_U[64 * R];                       // Lagrange basis at pixels

__device__ __forceinline__ uint32_t smem_u32(const void* p) {
    uint32_t a;
    asm("{ .reg .u64 t; cvta.to.shared.u64 t, %1; cvt.u32.u64 %0, t; }" : "=r"(a) : "l"(p));
    return a;
}
__device__ __forceinline__ void cp_async16(uint32_t dst, const void* src) {
    asm volatile("cp.async.cg.shared.global [%0], [%1], 16;\n" :: "r"(dst), "l"(src));
}
__device__ __forceinline__ void cp_commit() { asm volatile("cp.async.commit_group;\n" ::: "memory"); }
template <int N> __device__ __forceinline__ void cp_wait() {
    asm volatile("cp.async.wait_group %0;\n" :: "n"(N) : "memory");
}
__device__ __forceinline__ void ldsm_x4(uint32_t& r0, uint32_t& r1, uint32_t& r2, uint32_t& r3,
                                        uint32_t addr) {
    asm volatile("ldmatrix.sync.aligned.m8n8.x4.shared.b16 {%0,%1,%2,%3}, [%4];"
                 : "=r"(r0), "=r"(r1), "=r"(r2), "=r"(r3) : "r"(addr));
}

// ============================================================================
// Kernel 1: per-batch affine + per-channel params  (grid 16, 128 thr)
// ============================================================================
__global__ void k_setup(const float* __restrict__ w, const float* __restrict__ freqs,
                        const float* __restrict__ phases, const float* __restrict__ affine_w,
                        const float* __restrict__ affine_b) {
    __shared__ float t_sm[4];
    __shared__ float cs[4];
    int b = blockIdx.x;
    int tid = threadIdx.x, wid = tid >> 5, lane = tid & 31;

    float sum = 0.f;
    const float* wr = w + b * 512;
    const float* ar = affine_w + wid * 512;
    for (int j = lane; j < 512; j += 32) sum += wr[j] * ar[j];
    for (int o = 16; o; o >>= 1) sum += __shfl_xor_sync(0xffffffffu, sum, o);
    if (lane == 0) t_sm[wid] = sum * (1.0f / 22.627416997969522f) + affine_b[wid];
    __syncthreads();
    if (tid == 0) {
        float t0 = t_sm[0], t1 = t_sm[1], t2 = t_sm[2], t3 = t_sm[3];
        float inv = rsqrtf(t0 * t0 + t1 * t1);
        float c = t0 * inv, s = t1 * inv, tx = t2 * inv, ty = t3 * inv;
        cs[0] = c; cs[1] = s;
        cs[2] = -(c * tx - s * ty);   // trans_x
        cs[3] = -(s * tx + c * ty);   // trans_y
    }
    __syncthreads();
    float c = cs[0], s = cs[1], trx = cs[2], tryy = cs[3];
    const float TWO_PI = 6.283185307179586f;
    for (int ch = tid; ch < 1024; ch += 128) {
        float fx = freqs[ch * 2], fy = freqs[ch * 2 + 1];
        float ph = phases[ch] + fx * trx + fy * tryy;      // original freqs here
        float fbx = fx * c + fy * s;                        // f @ R
        float fby = -fx * s + fy * c;
        float r = sqrtf(fbx * fbx + fby * fby);
        float amp = 1.0f - (r - 2.0f) * (1.0f / 30.0f);
        amp = fminf(fmaxf(amp, 0.0f), 1.0f);
        g_params[b * 1024 + ch] = make_float4(fbx * TWO_PI, fby * TWO_PI, ph * TWO_PI, amp);
    }
}

// ============================================================================
// Kernel 2: weight -> fp16 * (1/sqrt(1024))
// ============================================================================
__global__ __launch_bounds__(256) void k_wt(const float* __restrict__ wt) {
    size_t i = (size_t)blockIdx.x * 256 + threadIdx.x;
    g_wt[i] = __float2half(wt[i] * 0.03125f);
}

// ============================================================================
// Kernel 3: Lagrange basis U[w][q] at Chebyshev nodes (barycentric, fp64)
// ============================================================================
__global__ void k_U() {
    int w = threadIdx.x;                       // 64 threads
    double x = (w + 0.5) / 64.0 - 0.5;
    double t[R], lam[R];
#pragma unroll
    for (int q = 0; q < R; q++) {
        double a = M_PI * (2 * q + 1) / (2.0 * R);
        t[q] = 0.5 * cos(a);
        lam[q] = ((q & 1) ? -1.0 : 1.0) * sin(a);
    }
    double D = 0.0;
#pragma unroll
    for (int q = 0; q < R; q++) D += lam[q] / (x - t[q]);
#pragma unroll
    for (int q = 0; q < R; q++)
        g_U[w * R + q] = (float)((lam[q] / (x - t[q])) / D);
}

// ============================================================================
// Kernel 4: virtual features at node pairs.  row m = b*256 + p*16 + q
//   grid (8 rchunk, 16 b) for occupancy.
// ============================================================================
__global__ __launch_bounds__(256) void k_vf() {
    __shared__ float ts[R];
    int b = blockIdx.y, r0 = blockIdx.x * 32, tid = threadIdx.x;
    if (tid < R) ts[tid] = 0.5f * cospif((2 * tid + 1) / (2.0f * R));
    __syncthreads();
    int c0 = tid * 4;
    float4 P[4];
#pragma unroll
    for (int j = 0; j < 4; j++) P[j] = g_params[b * 1024 + c0 + j];
    __half* outp = g_vfeat + (size_t)(b * 256 + r0) * 1024 + c0;
#pragma unroll 4
    for (int rr = 0; rr < 32; rr++) {
        int r = r0 + rr;
        float tq = ts[r & 15], tp = ts[r >> 4];
        float s0 = P[0].w * __sinf(P[0].x * tq + P[0].y * tp + P[0].z);
        float s1 = P[1].w * __sinf(P[1].x * tq + P[1].y * tp + P[1].z);
        float s2 = P[2].w * __sinf(P[2].x * tq + P[2].y * tp + P[2].z);
        float s3 = P[3].w * __sinf(P[3].x * tq + P[3].y * tp + P[3].z);
        union { __half2 h2[2]; uint2 u2; } cv;
        cv.h2[0] = __floats2half2_rn(s0, s1);
        cv.h2[1] = __floats2half2_rn(s2, s3);
        *reinterpret_cast<uint2*>(outp + (size_t)rr * 1024) = cv.u2;
    }
}

// ============================================================================
// Kernel 5: S-GEMM.  S[m,n] = sum_k vfeat[m,k]*wt[n,k].  M=4096,N=1024,K=1024
// ============================================================================
#define BM 128
#define BN 256
#define AROW 72
#define ROWB (AROW * 2)
#define A_TILE_H (BM * AROW)
#define B_TILE_H (BN * AROW)
#define STAGE_H (A_TILE_H + B_TILE_H)
#define NST 3
#define GEMM_SMEM (NST * STAGE_H * 2)

__device__ __forceinline__ void load_stage(uint32_t st, const __half* Ag,
                                           const __half* Bg, int tid) {
#pragma unroll
    for (int t = 0; t < 4; t++) {
        int cid = tid + t * 256;
        int row = cid >> 3, j = cid & 7;
        cp_async16(st + row * ROWB + j * 16, Ag + (size_t)row * 1024 + j * 8);
    }
    uint32_t stB = st + A_TILE_H * 2;
#pragma unroll
    for (int t = 0; t < 8; t++) {
        int cid = tid + t * 256;
        int row = cid >> 3, j = cid & 7;
        cp_async16(stB + row * ROWB + j * 16, Bg + (size_t)row * 1024 + j * 8);
    }
}

__global__ __launch_bounds__(256, 1) void k_gemm() {
    extern __shared__ __half smem_h[];
    uint32_t sb = smem_u32(smem_h);
    int tid = threadIdx.x, wid = tid >> 5, lane = tid & 31;
    int warp_m = wid >> 2, warp_n = wid & 3;
    int g = lane >> 2, kq = lane & 3;

    int n0 = blockIdx.x * BN;
    int m0 = blockIdx.y * BM;

    const __half* Abase = g_vfeat + (size_t)m0 * 1024;
    const __half* Bbase = g_wt + (size_t)n0 * 1024;

    const uint32_t a_lane_off = (uint32_t)(warp_m * 64 + (lane & 15)) * ROWB + (lane >> 4) * 16;
    const uint32_t b_lane_off = (uint32_t)(warp_n * 64 + (lane & 15)) * ROWB + (lane >> 4) * 16;

    float acc[4][8][4];
#pragma unroll
    for (int mt = 0; mt < 4; mt++)
#pragma unroll
        for (int nt = 0; nt < 8; nt++)
#pragma unroll
            for (int r = 0; r < 4; r++) acc[mt][nt][r] = 0.f;

    uint32_t afr[2][4][4], bfr[2][4][4];

    load_stage(sb, Abase, Bbase, tid);
    cp_commit();
    load_stage(sb + STAGE_H * 2, Abase + 64, Bbase + 64, tid);
    cp_commit();

#define LOAD_FRAGS(buf, abase_, bbase_, ksv)                                       \
    {                                                                              \
        _Pragma("unroll")                                                          \
        for (int mt = 0; mt < 4; mt++)                                             \
            ldsm_x4(afr[buf][mt][0], afr[buf][mt][1], afr[buf][mt][2],             \
                    afr[buf][mt][3], (abase_) + mt * (16 * ROWB) + (ksv) * 32);    \
        _Pragma("unroll")                                                          \
        for (int nb = 0; nb < 4; nb++)                                             \
            ldsm_x4(bfr[buf][nb][0], bfr[buf][nb][1], bfr[buf][nb][2],             \
                    bfr[buf][nb][3], (bbase_) + nb * (16 * ROWB) + (ksv) * 32);    \
    }

    for (int i = 0; i < 16; i++) {
        if (i < 15) cp_wait<1>(); else cp_wait<0>();
        __syncthreads();
        if (i + 2 < 16) {
            load_stage(sb + ((i + 2) % NST) * (STAGE_H * 2),
                       Abase + (size_t)(i + 2) * 64, Bbase + (size_t)(i + 2) * 64, tid);
            cp_commit();
        }
        uint32_t As = sb + (i % NST) * (STAGE_H * 2);
        uint32_t a_base = As + a_lane_off;
        uint32_t b_base = As + A_TILE_H * 2 + b_lane_off;

        LOAD_FRAGS(0, a_base, b_base, 0)
#pragma unroll
        for (int ks = 0; ks < 4; ks++) {
            int cur = ks & 1;
            if (ks < 3) LOAD_FRAGS(cur ^ 1, a_base, b_base, ks + 1)
#pragma unroll
            for (int mt = 0; mt < 4; mt++)
#pragma unroll
                for (int nt = 0; nt < 8; nt++)
                    asm volatile(
                        "mma.sync.aligned.m16n8k16.row.col.f32.f16.f16.f32 "
                        "{%0,%1,%2,%3}, {%4,%5,%6,%7}, {%8,%9}, {%0,%1,%2,%3};"
                        : "+f"(acc[mt][nt][0]), "+f"(acc[mt][nt][1]),
                          "+f"(acc[mt][nt][2]), "+f"(acc[mt][nt][3])
                        : "r"(afr[cur][mt][0]), "r"(afr[cur][mt][1]),
                          "r"(afr[cur][mt][2]), "r"(afr[cur][mt][3]),
                          "r"(bfr[cur][nt >> 1][nt & 1]),
                          "r"(bfr[cur][nt >> 1][(nt & 1) + 2]));
        }
    }

#pragma unroll
    for (int mt = 0; mt < 4; mt++) {
        int m_lo = m0 + warp_m * 64 + mt * 16 + g;
        float* o0 = g_S + (size_t)m_lo * 1024;
        float* o1 = o0 + 8 * 1024;
#pragma unroll
        for (int nt = 0; nt < 8; nt++) {
            int n = n0 + warp_n * 64 + nt * 8 + kq * 2;
            o0[n] = acc[mt][nt][0];
            o0[n + 1] = acc[mt][nt][1];
            o1[n] = acc[mt][nt][2];
            o1[n + 1] = acc[mt][nt][3];
        }
    }
}

// ============================================================================
// Kernel 6: separable interpolation, LDS-minimized.
//   Ss[p][nl][20] (pad 20 words -> float4 lane stride 20 banks, conflict-free)
//   UsT[q][w]     (q-major -> float4 broadcast, hoisted over 4 h rows)
//   thread (nl, hg): 8 h x 64 w for channel n0+nl, in 2 chunks of 4 h.
// ============================================================================
__global__ __launch_bounds__(256) void k_interp(float* __restrict__ out) {
    __shared__ __align__(16) float Ss[R][32][20];
    __shared__ __align__(16) float UsT[R][64];
    int b = blockIdx.y, n0 = blockIdx.x * 32;
    int tid = threadIdx.x;
    for (int idx = tid; idx < R * R * 32; idx += 256) {
        int p = idx >> 9, q = (idx >> 5) & 15, nl = idx & 31;
        Ss[p][nl][q] = g_S[(size_t)((b * 16 + p) * 16 + q) * 1024 + n0 + nl];
    }
    for (int idx = tid; idx < 64 * R; idx += 256)
        UsT[idx & 15][idx >> 4] = g_U[idx];
    __syncthreads();

    int nl = tid & 31, hg = tid >> 5;
    float* obase = out + ((size_t)(b * 1024 + n0 + nl)) * 4096;

#pragma unroll
    for (int hc = 0; hc < 2; hc++) {              // 2 chunks of 4 h rows
        int h0 = hg * 8 + hc * 4;
        // z[hh][q] for 4 rows
        float z[4][R];
#pragma unroll
        for (int hh = 0; hh < 4; hh++)
#pragma unroll
            for (int q = 0; q < R; q++) z[hh][q] = 0.f;
#pragma unroll
        for (int p = 0; p < R; p++) {
            const float4 s0 = *reinterpret_cast<const float4*>(&Ss[p][nl][0]);
            const float4 s1 = *reinterpret_cast<const float4*>(&Ss[p][nl][4]);
            const float4 s2 = *reinterpret_cast<const float4*>(&Ss[p][nl][8]);
            const float4 s3 = *reinterpret_cast<const float4*>(&Ss[p][nl][12]);
#pragma unroll
            for (int hh = 0; hh < 4; hh++) {
                float uh = UsT[p][h0 + hh];       // broadcast
                z[hh][0] += uh * s0.x;  z[hh][1] += uh * s0.y;
                z[hh][2] += uh * s0.z;  z[hh][3] += uh * s0.w;
                z[hh][4] += uh * s1.x;  z[hh][5] += uh * s1.y;
                z[hh][6] += uh * s1.z;  z[hh][7] += uh * s1.w;
                z[hh][8] += uh * s2.x;  z[hh][9] += uh * s2.y;
                z[hh][10] += uh * s2.z; z[hh][11] += uh * s2.w;
                z[hh][12] += uh * s3.x; z[hh][13] += uh * s3.y;
                z[hh][14] += uh * s3.z; z[hh][15] += uh * s3.w;
            }
        }
        // w-pass: for each w-quad, one broadcast float4 of UsT serves 4 h rows
#pragma unroll 2
        for (int wq = 0; wq < 16; wq++) {
            float4 a[4];
#pragma unroll
            for (int hh = 0; hh < 4; hh++) a[hh] = make_float4(0.f, 0.f, 0.f, 0.f);
#pragma unroll
            for (int q = 0; q < R; q++) {
                const float4 u4 = *reinterpret_cast<const float4*>(&UsT[q][wq * 4]);
#pragma unroll
                for (int hh = 0; hh < 4; hh++) {
                    float zq = z[hh][q];
                    a[hh].x += zq * u4.x;  a[hh].y += zq * u4.y;
                    a[hh].z += zq * u4.z;  a[hh].w += zq * u4.w;
                }
            }
#pragma unroll
            for (int hh = 0; hh < 4; hh++)
                *reinterpret_cast<float4*>(obase + (h0 + hh) * 64 + wq * 4) = a[hh];
        }
    }
}

// ============================================================================
// launch
// ============================================================================
extern "C" void kernel_launch(void* const* d_in, const int* in_sizes, int n_in,
                              void* d_out, int out_size) {
    const float* w        = (const float*)d_in[0];
    const float* freqs    = (const float*)d_in[1];
    const float* phases   = (const float*)d_in[2];
    const float* weight   = (const float*)d_in[3];
    const float* affine_w = (const float*)d_in[4];
    const float* affine_b = (const float*)d_in[5];
    float* out = (float*)d_out;

    cudaFuncSetAttribute(k_gemm, cudaFuncAttributeMaxDynamicSharedMemorySize, GEMM_SMEM);

    k_setup<<<16, 128>>>(w, freqs, phases, affine_w, affine_b);
    k_wt<<<4096, 256>>>(weight);
    k_U<<<1, 64>>>();
    k_vf<<<dim3(8, 16), 256>>>();
    k_gemm<<<dim3(4, 32), 256, GEMM_SMEM>>>();
    k_interp<<<dim3(32, 16), 256>>>(out);
}